// round 16
// baseline (speedup 1.0000x reference)
#include <cuda_runtime.h>
#include <cuda_bf16.h>
#include <cuda_fp16.h>
#include <math.h>
#include <stdint.h>

#define N_NODES 100000
#define N_EDGES 1600000
#define N_GRAPHS 64
#define EPSF 1e-7f

#define SCAN_B 1024
#define NB_SCAN ((N_NODES + SCAN_B - 1) / SCAN_B)   // 98
#define NB_H 6250      // N_EDGES / 256
#define NB_X 12500     // N_NODES*128/4 / 256
#define NB_G 391       // ceil(N_NODES / 256)

// ---------------- scratch (device globals, device-side access ONLY) --------
__device__ int   g_deg[N_NODES];
__device__ int   g_rowstart[N_NODES];
__device__ int   g_cursor[N_NODES];
__device__ int   g_csr_src[N_EDGES];
__device__ int   g_blocksums[128];
__device__ int   g_gstart[N_GRAPHS + 1];
// ping-pong fp32 residual / output buffers (each fused layer reads one, writes other)
__device__ __align__(16) float g_C0[(size_t)N_NODES * 192];
__device__ __align__(16) float g_C1[(size_t)N_NODES * 192];
// ping-pong fp16 pre-relu'd gather sources
__device__ __align__(16) __half g_h0[(size_t)N_NODES * 192];
__device__ __align__(16) __half g_h1[(size_t)N_NODES * 192];
// split-bf16 transposed weights [layer][DO*K]
__device__ __align__(16) __nv_bfloat16 g_w1tA[4][192 * 192];
__device__ __align__(16) __nv_bfloat16 g_w2tA[4][192 * 192];
// pool partials
__device__ float g_pool_sum4[4 * N_GRAPHS * 128];

__device__ __forceinline__ uint32_t packbf(float a, float b) {
    __nv_bfloat162 t = __floats2bfloat162_rn(a, b);
    return *(uint32_t*)&t;
}
__device__ __forceinline__ uint32_t packh_relu(float a, float b) {
    __half2 t = __floats2half2_rn(fmaxf(a, 0.f), fmaxf(b, 0.f));
    return *(uint32_t*)&t;
}
__device__ __forceinline__ float2 h2f(uint32_t u) {
    return __half22float2(*(__half2*)&u);
}
__device__ __forceinline__ uint32_t hacc2(uint32_t a, uint32_t b) {
    __half2 r = __hadd2(*(__half2*)&a, *(__half2*)&b);
    return *(uint32_t*)&r;
}
__device__ __forceinline__ void ldsm_x4(uint32_t (&r)[4], uint32_t saddr) {
    asm volatile("ldmatrix.sync.aligned.m8n8.x4.shared.b16 {%0,%1,%2,%3}, [%4];"
        : "=r"(r[0]), "=r"(r[1]), "=r"(r[2]), "=r"(r[3]) : "r"(saddr));
}

// ---------------- k_prep: hist (g_deg) + relu'd fp16 x copy + gstart -------
__global__ void k_prep(const int* __restrict__ dst, const float* __restrict__ x,
                       const int* __restrict__ batch) {
    int b = blockIdx.x;
    if (b < NB_H) {
        int i = b * 256 + threadIdx.x;
        if (i < N_EDGES) atomicAdd(&g_deg[dst[i]], 1);
    } else if (b < NB_H + NB_X) {
        int i = (b - NB_H) * 256 + threadIdx.x;     // over N*128/4
        if (i < N_NODES * 32) {
            float4 v = __ldg((const float4*)x + i);
            uint2 o = make_uint2(packh_relu(v.x, v.y), packh_relu(v.z, v.w));
            *(uint2*)((char*)g_h0 + (size_t)i * 8) = o;
        }
    } else {
        int i = (b - NB_H - NB_X) * 256 + threadIdx.x;
        if (i < N_NODES) {
            int bb = batch[i];
            int bp = (i == 0) ? -1 : batch[i - 1];
            for (int g = bp + 1; g <= bb; g++) g_gstart[g] = i;
            if (i == N_NODES - 1)
                for (int g = bb + 1; g <= N_GRAPHS; g++) g_gstart[g] = N_NODES;
        }
    }
}

// ---------------- 3-kernel parallel scan (coalesced, proven) ---------------
__global__ void k_scan1() {
    int idx = blockIdx.x * SCAN_B + threadIdx.x;
    int v = (idx < N_NODES) ? g_deg[idx] : 0;
    int lane = threadIdx.x & 31, w = threadIdx.x >> 5;
    int x = v;
    #pragma unroll
    for (int o = 1; o < 32; o <<= 1) {
        int t = __shfl_up_sync(0xffffffffu, x, o);
        if (lane >= o) x += t;
    }
    __shared__ int wsum[32];
    if (lane == 31) wsum[w] = x;
    __syncthreads();
    if (w == 0) {
        int y = wsum[lane];
        #pragma unroll
        for (int o = 1; o < 32; o <<= 1) {
            int t = __shfl_up_sync(0xffffffffu, y, o);
            if (lane >= o) y += t;
        }
        wsum[lane] = y;
    }
    __syncthreads();
    int incl = x + (w > 0 ? wsum[w - 1] : 0);
    if (idx < N_NODES) g_rowstart[idx] = incl - v;
    if (threadIdx.x == SCAN_B - 1) g_blocksums[blockIdx.x] = incl;
}

__global__ void k_scan2() {
    int t = threadIdx.x;
    int v = (t < NB_SCAN) ? g_blocksums[t] : 0;
    int lane = t & 31, w = t >> 5;
    int x = v;
    #pragma unroll
    for (int o = 1; o < 32; o <<= 1) {
        int tt = __shfl_up_sync(0xffffffffu, x, o);
        if (lane >= o) x += tt;
    }
    __shared__ int ws[4];
    if (lane == 31) ws[w] = x;
    __syncthreads();
    if (t == 0) {
        int a = 0;
        #pragma unroll
        for (int i = 0; i < 4; i++) { int tmp = ws[i]; ws[i] = a; a += tmp; }
    }
    __syncthreads();
    int incl = x + ws[w];
    if (t < 128) g_blocksums[t] = incl - v;
}

__global__ void k_scan3() {
    int idx = blockIdx.x * SCAN_B + threadIdx.x;
    if (idx < N_NODES) {
        int r = g_rowstart[idx] + g_blocksums[idx >> 10];
        g_rowstart[idx] = r;
        g_cursor[idx] = r;
    }
}

__global__ void k_fill(const int* __restrict__ src, const int* __restrict__ dst) {
    int i = blockIdx.x * blockDim.x + threadIdx.x;
    if (i < N_EDGES) {
        int p = atomicAdd(&g_cursor[dst[i]], 1);
        g_csr_src[p] = src[i];
    }
}

// ---------------- k_wprepall: all 4 layers' W -> split bf16 [DO][K] --------
__global__ void k_wprepall(const float* __restrict__ W0, const float* __restrict__ W1,
                           const float* __restrict__ W2, const float* __restrict__ W3) {
    int i = blockIdx.x * blockDim.x + threadIdx.x;
    const float* W; int K, DO, l, idx;
    if (i < 24576)       { W = W0; K = 128; DO = 192; l = 0; idx = i; }
    else if (i < 61440)  { W = W1; K = 192; DO = 192; l = 1; idx = i - 24576; }
    else if (i < 98304)  { W = W2; K = 192; DO = 192; l = 2; idx = i - 61440; }
    else if (i < 122880) { W = W3; K = 192; DO = 128; l = 3; idx = i - 98304; }
    else return;
    int k = idx / DO, n = idx % DO;
    float w = W[idx];
    __nv_bfloat16 h = __float2bfloat16(w);
    float r = w - __bfloat162float(h);
    g_w1tA[l][n * K + k] = h;
    g_w2tA[l][n * K + k] = __float2bfloat16(r);
}

// ---------------- fused layer: agg (-> smem split-bf16 A) + HMMA GEMM ------
// reads h[hsel] (gather) and residual (xext or C[hsel]); writes C[1-hsel], h[1-hsel].
#define MMA_BF16(d, a, b0_, b1_) \
    asm volatile("mma.sync.aligned.m16n8k16.row.col.f32.bf16.bf16.f32 " \
        "{%0,%1,%2,%3}, {%4,%5,%6,%7}, {%8,%9}, {%0,%1,%2,%3};" \
        : "+f"((d)[0]), "+f"((d)[1]), "+f"((d)[2]), "+f"((d)[3]) \
        : "r"((a)[0]), "r"((a)[1]), "r"((a)[2]), "r"((a)[3]), \
          "r"(b0_), "r"(b1_))

template <int K, int DO>
__global__ __launch_bounds__(512) void k_fused(const float* __restrict__ xext,
                                               const float* __restrict__ bias,
                                               int wl, int hsel) {
    constexpr int SL = K / 8;        // slices per node (16 or 24)
    constexpr int NCHUNK = K / 32;   // 32-k planes (4 or 6)
    constexpr int NBN = DO / 64;     // N tiles (2 or 3)
    extern __shared__ char sm[];
    char* A1s = sm;
    char* A2s = sm + NCHUNK * 10240;
    char* B1s = sm + 2 * NCHUNK * 10240;
    char* B2s = B1s + 5120;

    const __half* hs = hsel ? g_h1 : g_h0;
    __half* hd = hsel ? g_h0 : g_h1;
    const float* Xres = xext ? xext : (hsel ? (const float*)g_C1 : (const float*)g_C0);
    float* C = hsel ? g_C0 : g_C1;
    const __nv_bfloat16* w1t = g_w1tA[wl];
    const __nv_bfloat16* w2t = g_w2tA[wl];

    int tid = threadIdx.x;
    int bm = blockIdx.x * 128;

    // ---- phase 1: aggregate 128 nodes into smem A planes (split-bf16) ----
    for (int task = tid; task < 128 * SL; task += 512) {
        int r = task / SL, s = task - r * SL;
        int n = bm + r;
        uint32_t hi[4] = {0u, 0u, 0u, 0u}, lo[4] = {0u, 0u, 0u, 0u};
        if (n < N_NODES) {
            const char* hb = (const char*)hs + s * 16;
            const int* csr = g_csr_src + g_rowstart[n];
            int deg = g_deg[n];
            float accf[8];
            #pragma unroll
            for (int i = 0; i < 8; i++) accf[i] = 0.f;
            int e = 0;
            for (; e + 8 <= deg; e += 8) {
                uint32_t a0 = 0, a1 = 0, a2 = 0, a3 = 0;
                #pragma unroll
                for (int k = 0; k < 8; k++) {
                    int idx = __ldg(csr + e + k);
                    uint4 v = __ldg((const uint4*)(hb + (size_t)idx * (K * 2)));
                    a0 = hacc2(a0, v.x); a1 = hacc2(a1, v.y);
                    a2 = hacc2(a2, v.z); a3 = hacc2(a3, v.w);
                }
                float2 f0 = h2f(a0), f1 = h2f(a1), f2 = h2f(a2), f3 = h2f(a3);
                accf[0] += f0.x; accf[1] += f0.y; accf[2] += f1.x; accf[3] += f1.y;
                accf[4] += f2.x; accf[5] += f2.y; accf[6] += f3.x; accf[7] += f3.y;
            }
            if (e < deg) {
                uint32_t a0 = 0, a1 = 0, a2 = 0, a3 = 0;
                for (; e < deg; e++) {
                    int idx = __ldg(csr + e);
                    uint4 v = __ldg((const uint4*)(hb + (size_t)idx * (K * 2)));
                    a0 = hacc2(a0, v.x); a1 = hacc2(a1, v.y);
                    a2 = hacc2(a2, v.z); a3 = hacc2(a3, v.w);
                }
                float2 f0 = h2f(a0), f1 = h2f(a1), f2 = h2f(a2), f3 = h2f(a3);
                accf[0] += f0.x; accf[1] += f0.y; accf[2] += f1.x; accf[3] += f1.y;
                accf[4] += f2.x; accf[5] += f2.y; accf[6] += f3.x; accf[7] += f3.y;
            }
            float ep = (float)deg * EPSF;
            const float4* xr = (const float4*)(Xres + (size_t)n * K + s * 8);
            float4 x0 = __ldg(xr);
            float4 x1 = __ldg(xr + 1);
            float y[8];
            y[0] = x0.x + accf[0] + ep; y[1] = x0.y + accf[1] + ep;
            y[2] = x0.z + accf[2] + ep; y[3] = x0.w + accf[3] + ep;
            y[4] = x1.x + accf[4] + ep; y[5] = x1.y + accf[5] + ep;
            y[6] = x1.z + accf[6] + ep; y[7] = x1.w + accf[7] + ep;
            #pragma unroll
            for (int q = 0; q < 4; q++) {
                float a = y[q * 2], b = y[q * 2 + 1];
                hi[q] = packbf(a, b);
                float2 f = __bfloat1622float2(*(__nv_bfloat162*)&hi[q]);
                lo[q] = packbf(a - f.x, b - f.y);
            }
        }
        int c = s >> 2, ch = s & 3;
        *(uint4*)(A1s + c * 10240 + r * 80 + ch * 16) = make_uint4(hi[0], hi[1], hi[2], hi[3]);
        *(uint4*)(A2s + c * 10240 + r * 80 + ch * 16) = make_uint4(lo[0], lo[1], lo[2], lo[3]);
    }
    __syncthreads();

    // ---- phase 2: GEMM over bn tiles, reusing smem A ----
    int lane = tid & 31, wid = tid >> 5;        // 16 warps
    int g = lane >> 2, t = lane & 3;
    int wm = wid & 7;        // 8 M-tiles of 16 rows
    int wn = wid >> 3;       // 2 N-tiles of 32 cols
    uint32_t sA1 = (uint32_t)__cvta_generic_to_shared(A1s);
    uint32_t sA2 = (uint32_t)__cvta_generic_to_shared(A2s);
    uint32_t sB1 = (uint32_t)__cvta_generic_to_shared(B1s);
    uint32_t sB2 = (uint32_t)__cvta_generic_to_shared(B2s);
    uint32_t laneA = (uint32_t)((lane & 15) * 80 + (lane >> 4) * 16);
    uint32_t laneB = (uint32_t)((lane & 7) * 80 + ((lane >> 3) & 1) * 16 +
                                (lane >> 4) * (8 * 80));

    for (int bnt = 0; bnt < NBN; bnt++) {
        float acc[4][4];
        #pragma unroll
        for (int j = 0; j < 4; j++)
            #pragma unroll
            for (int q = 0; q < 4; q++) acc[j][q] = 0.f;

        for (int c = 0; c < NCHUNK; c++) {
            __syncthreads();
            {   // 512 threads load both B splits: half 0 -> B1s, half 1 -> B2s
                int half = tid >> 8;
                int row = (tid >> 2) & 63, ch = tid & 3;
                size_t gb = ((size_t)(bnt * 64 + row) * K + c * 32) * 2 + ch * 16;
                const char* wsrc = half ? (const char*)w2t : (const char*)w1t;
                char* bdst = half ? B2s : B1s;
                *(uint4*)(bdst + row * 80 + ch * 16) = __ldg((const uint4*)(wsrc + gb));
            }
            __syncthreads();

            #pragma unroll
            for (int ks = 0; ks < 2; ks++) {
                uint32_t kb = (uint32_t)(ks * 32);
                uint32_t a1f[4], a2f[4];
                uint32_t ab = (uint32_t)(c * 10240 + (wm * 16) * 80) + kb + laneA;
                ldsm_x4(a1f, sA1 + ab);
                ldsm_x4(a2f, sA2 + ab);
                uint32_t bv1[2][4], bv2[2][4];
                #pragma unroll
                for (int p = 0; p < 2; p++) {
                    uint32_t bb = (uint32_t)((wn * 32 + p * 16) * 80) + kb + laneB;
                    ldsm_x4(bv1[p], sB1 + bb);
                    ldsm_x4(bv2[p], sB2 + bb);
                }
                #pragma unroll
                for (int nt = 0; nt < 4; nt++) {
                    uint32_t b10 = bv1[nt >> 1][(nt & 1) * 2];
                    uint32_t b11 = bv1[nt >> 1][(nt & 1) * 2 + 1];
                    uint32_t b20 = bv2[nt >> 1][(nt & 1) * 2];
                    uint32_t b21 = bv2[nt >> 1][(nt & 1) * 2 + 1];
                    MMA_BF16(acc[nt], a1f, b10, b11);
                    MMA_BF16(acc[nt], a1f, b20, b21);
                    MMA_BF16(acc[nt], a2f, b10, b11);
                }
            }
        }

        // epilogue for this bn tile: fp32 C + relu'd fp16 into hd
        #pragma unroll
        for (int nt = 0; nt < 4; nt++) {
            int col = bnt * 64 + wn * 32 + nt * 8 + 2 * t;
            float2 bv = *(const float2*)(bias + col);
            int r0 = bm + wm * 16 + g;
            if (r0 < N_NODES) {
                float2 o = make_float2(acc[nt][0] + bv.x, acc[nt][1] + bv.y);
                *(float2*)(C + (size_t)r0 * DO + col) = o;
                *(uint32_t*)((char*)hd + ((size_t)r0 * DO + col) * 2) = packh_relu(o.x, o.y);
            }
            int r1 = r0 + 8;
            if (r1 < N_NODES) {
                float2 o = make_float2(acc[nt][2] + bv.x, acc[nt][3] + bv.y);
                *(float2*)(C + (size_t)r1 * DO + col) = o;
                *(uint32_t*)((char*)hd + ((size_t)r1 * DO + col) * 2) = packh_relu(o.x, o.y);
            }
        }
    }
}

// ---------------- pooling (+ tail re-zero of g_deg for next call) ----------
__global__ void k_pool() {
    int gid = ((blockIdx.y * gridDim.x + blockIdx.x) * blockDim.x) + threadIdx.x;
    int nthreads = gridDim.x * gridDim.y * blockDim.x;   // 32768
    for (int i = gid; i < N_NODES; i += nthreads) g_deg[i] = 0;

    const float* H = g_C0;                   // final layer output, d=128
    int g = blockIdx.x, chunk = blockIdx.y;  // 64 x 4
    int s = g_gstart[g], e = g_gstart[g + 1];
    int len = e - s;
    int n0 = s + (len * chunk) / 4;
    int n1 = s + (len * (chunk + 1)) / 4;
    int f = threadIdx.x;                     // 128 features
    float a0 = 0.f, a1 = 0.f, a2 = 0.f, a3 = 0.f;
    int n = n0;
    for (; n + 4 <= n1; n += 4) {
        a0 += __ldg(H + (size_t)(n + 0) * 128 + f);
        a1 += __ldg(H + (size_t)(n + 1) * 128 + f);
        a2 += __ldg(H + (size_t)(n + 2) * 128 + f);
        a3 += __ldg(H + (size_t)(n + 3) * 128 + f);
    }
    for (; n < n1; n++) a0 += __ldg(H + (size_t)n * 128 + f);
    g_pool_sum4[(chunk * N_GRAPHS + g) * 128 + f] = (a0 + a1) + (a2 + a3);
}

__global__ void k_head(const float* __restrict__ Wfc, const float* __restrict__ bfc,
                       float* __restrict__ out) {
    __shared__ float s_logit[N_GRAPHS][10];
    __shared__ float s_lse[N_GRAPHS];
    int tid = threadIdx.x;                   // 640 threads
    int g = tid / 10, j = tid % 10;
    float cnt = fmaxf((float)(g_gstart[g + 1] - g_gstart[g]), 1.f);
    float acc = bfc[j];
    #pragma unroll 8
    for (int f = 0; f < 128; f++) {
        float s = g_pool_sum4[(0 * N_GRAPHS + g) * 128 + f]
                + g_pool_sum4[(1 * N_GRAPHS + g) * 128 + f]
                + g_pool_sum4[(2 * N_GRAPHS + g) * 128 + f]
                + g_pool_sum4[(3 * N_GRAPHS + g) * 128 + f];
        acc += (s / cnt) * Wfc[f * 10 + j];
    }
    s_logit[g][j] = acc;
    __syncthreads();
    if (j == 0) {
        float m = -1e30f;
        #pragma unroll
        for (int t = 0; t < 10; t++) m = fmaxf(m, s_logit[g][t]);
        float s = 0.f;
        #pragma unroll
        for (int t = 0; t < 10; t++) s += expf(s_logit[g][t] - m);
        s_lse[g] = m + logf(s);
    }
    __syncthreads();
    out[g * 10 + j] = s_logit[g][j] - s_lse[g];
}

// ---------------- launch ----------------
extern "C" void kernel_launch(void* const* d_in, const int* in_sizes, int n_in,
                              void* d_out, int out_size) {
    const float* x   = (const float*)d_in[0];
    const float* W0  = (const float*)d_in[1];
    const float* b0  = (const float*)d_in[2];
    const float* W1  = (const float*)d_in[3];
    const float* b1  = (const float*)d_in[4];
    const float* W2  = (const float*)d_in[5];
    const float* b2  = (const float*)d_in[6];
    const float* W3  = (const float*)d_in[7];
    const float* b3  = (const float*)d_in[8];
    const float* Wfc = (const float*)d_in[9];
    const float* bfc = (const float*)d_in[10];
    const int* ei    = (const int*)d_in[11];
    const int* batch = (const int*)d_in[12];
    const int* src = ei;
    const int* dst = ei + N_EDGES;
    float* out = (float*)d_out;

    const int SM_128 = 2 * 4 * 10240 + 2 * 5120;   // 92160
    const int SM_192 = 2 * 6 * 10240 + 2 * 5120;   // 133120
    cudaFuncSetAttribute(k_fused<128, 192>, cudaFuncAttributeMaxDynamicSharedMemorySize, SM_128);
    cudaFuncSetAttribute(k_fused<192, 192>, cudaFuncAttributeMaxDynamicSharedMemorySize, SM_192);
    cudaFuncSetAttribute(k_fused<192, 128>, cudaFuncAttributeMaxDynamicSharedMemorySize, SM_192);

    int fgrid = (N_NODES + 127) / 128;   // 782

    k_prep<<<NB_H + NB_X + NB_G, 256>>>(dst, x, batch);            // 0
    k_scan1<<<NB_SCAN, SCAN_B>>>();                                // 1
    k_scan2<<<1, 128>>>();                                         // 2
    k_scan3<<<NB_SCAN, SCAN_B>>>();                                // 3
    k_fill<<<(N_EDGES + 255) / 256, 256>>>(src, dst);              // 4
    k_wprepall<<<480, 256>>>(W0, W1, W2, W3);                      // 5
    // L1: read g_h0 + x       -> write g_C1, g_h1
    k_fused<128, 192><<<fgrid, 512, SM_128>>>(x, b0, 0, 0);        // 6
    // L2: read g_h1 + g_C1    -> write g_C0, g_h0
    k_fused<192, 192><<<fgrid, 512, SM_192>>>(nullptr, b1, 1, 1);  // 7
    // L3: read g_h0 + g_C0    -> write g_C1, g_h1
    k_fused<192, 192><<<fgrid, 512, SM_192>>>(nullptr, b2, 2, 0);  // 8
    // L4: read g_h1 + g_C1    -> write g_C0, g_h0
    k_fused<192, 128><<<fgrid, 512, SM_192>>>(nullptr, b3, 3, 1);  // 9
    dim3 pool_grid(N_GRAPHS, 4);
    k_pool<<<pool_grid, 128>>>();                                  // 10
    k_head<<<1, 640>>>(Wfc, bfc, out);                             // 11
}

// round 17
// speedup vs baseline: 1.2032x; 1.2032x over previous
#include <cuda_runtime.h>
#include <cuda_bf16.h>
#include <cuda_fp16.h>
#include <math.h>
#include <stdint.h>

#define N_NODES 100000
#define N_EDGES 1600000
#define N_GRAPHS 64
#define EPSF 1e-7f

#define SCAN_B 1024
#define NB_SCAN ((N_NODES + SCAN_B - 1) / SCAN_B)   // 98
#define NB_H 6250      // N_EDGES / 256
#define NB_X 12500     // N_NODES*128/4 / 256
#define NB_G 391       // ceil(N_NODES / 256)

// ---------------- scratch (device globals, device-side access ONLY) --------
// g_deg is zero-initialized at module load; k_pool re-zeroes it at the END of
// every kernel_launch so each call sees the same state.
__device__ int   g_deg[N_NODES];
__device__ int   g_rowstart[N_NODES];
__device__ int   g_cursor[N_NODES];
__device__ int   g_csr_src[N_EDGES];
__device__ int   g_blocksums[128];
__device__ int   g_gstart[N_GRAPHS + 1];
// fp32 GEMM output (layer i) -> residual/pool input
__device__ __align__(16) float g_bufC[(size_t)N_NODES * 192];
// fp16 PRE-RELU'D node features: gather source for agg.
// Written ONLY by k_prep (layer 1) and k_gemm epilogue (layers 2-4); k_agg READ-ONLY.
__device__ __align__(16) __half g_h[(size_t)N_NODES * 192];
// split-bf16 activations (GEMM A operand), row stride = layer K
__device__ __align__(16) __nv_bfloat16 g_a1[(size_t)N_NODES * 192];
__device__ __align__(16) __nv_bfloat16 g_a2[(size_t)N_NODES * 192];
// split-bf16 transposed weights [layer][DO*K]
__device__ __align__(16) __nv_bfloat16 g_w1tA[4][192 * 192];
__device__ __align__(16) __nv_bfloat16 g_w2tA[4][192 * 192];
// pool partials: [chunk][graph][feature], summed in head (no atomics)
__device__ float g_pool_sum4[4 * N_GRAPHS * 128];

__device__ __forceinline__ uint32_t packbf(float a, float b) {
    __nv_bfloat162 t = __floats2bfloat162_rn(a, b);
    return *(uint32_t*)&t;
}
__device__ __forceinline__ uint32_t packh_relu(float a, float b) {
    __half2 t = __floats2half2_rn(fmaxf(a, 0.f), fmaxf(b, 0.f));
    return *(uint32_t*)&t;
}
__device__ __forceinline__ float2 h2f(uint32_t u) {
    return __half22float2(*(__half2*)&u);
}
__device__ __forceinline__ uint32_t hacc2(uint32_t a, uint32_t b) {
    __half2 r = __hadd2(*(__half2*)&a, *(__half2*)&b);
    return *(uint32_t*)&r;
}
__device__ __forceinline__ void ldsm_x4(uint32_t (&r)[4], uint32_t saddr) {
    asm volatile("ldmatrix.sync.aligned.m8n8.x4.shared.b16 {%0,%1,%2,%3}, [%4];"
        : "=r"(r[0]), "=r"(r[1]), "=r"(r[2]), "=r"(r[3]) : "r"(saddr));
}

// ---------------- k_prep: hist (g_deg) + relu'd fp16 x copy + gstart -------
__global__ void k_prep(const int* __restrict__ dst, const float* __restrict__ x,
                       const int* __restrict__ batch) {
    int b = blockIdx.x;
    if (b < NB_H) {
        int i = b * 256 + threadIdx.x;
        if (i < N_EDGES) atomicAdd(&g_deg[dst[i]], 1);
    } else if (b < NB_H + NB_X) {
        int i = (b - NB_H) * 256 + threadIdx.x;     // over N*128/4
        if (i < N_NODES * 32) {
            float4 v = __ldg((const float4*)x + i);
            uint2 o = make_uint2(packh_relu(v.x, v.y), packh_relu(v.z, v.w));
            *(uint2*)((char*)g_h + (size_t)i * 8) = o;
        }
    } else {
        int i = (b - NB_H - NB_X) * 256 + threadIdx.x;
        if (i < N_NODES) {
            int bb = batch[i];
            int bp = (i == 0) ? -1 : batch[i - 1];
            for (int g = bp + 1; g <= bb; g++) g_gstart[g] = i;
            if (i == N_NODES - 1)
                for (int g = bb + 1; g <= N_GRAPHS; g++) g_gstart[g] = N_NODES;
        }
    }
}

// ---------------- 3-kernel parallel scan (coalesced, proven) ---------------
__global__ void k_scan1() {
    int idx = blockIdx.x * SCAN_B + threadIdx.x;
    int v = (idx < N_NODES) ? g_deg[idx] : 0;
    int lane = threadIdx.x & 31, w = threadIdx.x >> 5;
    int x = v;
    #pragma unroll
    for (int o = 1; o < 32; o <<= 1) {
        int t = __shfl_up_sync(0xffffffffu, x, o);
        if (lane >= o) x += t;
    }
    __shared__ int wsum[32];
    if (lane == 31) wsum[w] = x;
    __syncthreads();
    if (w == 0) {
        int y = wsum[lane];
        #pragma unroll
        for (int o = 1; o < 32; o <<= 1) {
            int t = __shfl_up_sync(0xffffffffu, y, o);
            if (lane >= o) y += t;
        }
        wsum[lane] = y;
    }
    __syncthreads();
    int incl = x + (w > 0 ? wsum[w - 1] : 0);
    if (idx < N_NODES) g_rowstart[idx] = incl - v;
    if (threadIdx.x == SCAN_B - 1) g_blocksums[blockIdx.x] = incl;
}

__global__ void k_scan2() {
    int t = threadIdx.x;
    int v = (t < NB_SCAN) ? g_blocksums[t] : 0;
    int lane = t & 31, w = t >> 5;
    int x = v;
    #pragma unroll
    for (int o = 1; o < 32; o <<= 1) {
        int tt = __shfl_up_sync(0xffffffffu, x, o);
        if (lane >= o) x += tt;
    }
    __shared__ int ws[4];
    if (lane == 31) ws[w] = x;
    __syncthreads();
    if (t == 0) {
        int a = 0;
        #pragma unroll
        for (int i = 0; i < 4; i++) { int tmp = ws[i]; ws[i] = a; a += tmp; }
    }
    __syncthreads();
    int incl = x + ws[w];
    if (t < 128) g_blocksums[t] = incl - v;
}

__global__ void k_scan3() {
    int idx = blockIdx.x * SCAN_B + threadIdx.x;
    if (idx < N_NODES) {
        int r = g_rowstart[idx] + g_blocksums[idx >> 10];
        g_rowstart[idx] = r;
        g_cursor[idx] = r;
    }
}

__global__ void k_fill(const int* __restrict__ src, const int* __restrict__ dst) {
    int i = blockIdx.x * blockDim.x + threadIdx.x;
    if (i < N_EDGES) {
        int p = atomicAdd(&g_cursor[dst[i]], 1);
        g_csr_src[p] = src[i];
    }
}

// ---------------- aggregation v2 (R14-proven): thread-per-(node, slice) ----
template <int D>
__global__ void k_agg(const float* __restrict__ xext) {
    constexpr int SL = D / 8;                // threads per node: 16 or 24
    int t = blockIdx.x * blockDim.x + threadIdx.x;
    int n = t / SL;
    if (n >= N_NODES) return;
    int s = t - n * SL;
    const float* X = xext ? xext : (const float*)g_bufC;
    const char* hb = (const char*)g_h + s * 16;   // slice offset within row
    const int* csr = g_csr_src + g_rowstart[n];
    int deg = g_deg[n];

    float accf[8];
    #pragma unroll
    for (int i = 0; i < 8; i++) accf[i] = 0.f;

    int e = 0;
    for (; e + 8 <= deg; e += 8) {
        uint32_t a0 = 0, a1 = 0, a2 = 0, a3 = 0;
        #pragma unroll
        for (int k = 0; k < 4; k++) {
            int idx = __ldg(csr + e + k);
            uint4 v = __ldg((const uint4*)(hb + (size_t)idx * (D * 2)));
            a0 = hacc2(a0, v.x); a1 = hacc2(a1, v.y);
            a2 = hacc2(a2, v.z); a3 = hacc2(a3, v.w);
        }
        #pragma unroll
        for (int k = 4; k < 8; k++) {
            int idx = __ldg(csr + e + k);
            uint4 v = __ldg((const uint4*)(hb + (size_t)idx * (D * 2)));
            a0 = hacc2(a0, v.x); a1 = hacc2(a1, v.y);
            a2 = hacc2(a2, v.z); a3 = hacc2(a3, v.w);
        }
        float2 f0 = h2f(a0), f1 = h2f(a1), f2 = h2f(a2), f3 = h2f(a3);
        accf[0] += f0.x; accf[1] += f0.y; accf[2] += f1.x; accf[3] += f1.y;
        accf[4] += f2.x; accf[5] += f2.y; accf[6] += f3.x; accf[7] += f3.y;
    }
    if (e < deg) {
        uint32_t a0 = 0, a1 = 0, a2 = 0, a3 = 0;
        for (; e < deg; e++) {
            int idx = __ldg(csr + e);
            uint4 v = __ldg((const uint4*)(hb + (size_t)idx * (D * 2)));
            a0 = hacc2(a0, v.x); a1 = hacc2(a1, v.y);
            a2 = hacc2(a2, v.z); a3 = hacc2(a3, v.w);
        }
        float2 f0 = h2f(a0), f1 = h2f(a1), f2 = h2f(a2), f3 = h2f(a3);
        accf[0] += f0.x; accf[1] += f0.y; accf[2] += f1.x; accf[3] += f1.y;
        accf[4] += f2.x; accf[5] += f2.y; accf[6] += f3.x; accf[7] += f3.y;
    }

    // epilogue: residual + eps, pack split-bf16
    float ep = (float)deg * EPSF;
    const float4* xr = (const float4*)(X + (size_t)n * D + s * 8);
    float4 x0 = __ldg(xr);
    float4 x1 = __ldg(xr + 1);
    float y[8];
    y[0] = x0.x + accf[0] + ep; y[1] = x0.y + accf[1] + ep;
    y[2] = x0.z + accf[2] + ep; y[3] = x0.w + accf[3] + ep;
    y[4] = x1.x + accf[4] + ep; y[5] = x1.y + accf[5] + ep;
    y[6] = x1.z + accf[6] + ep; y[7] = x1.w + accf[7] + ep;

    uint32_t hi[4], lo[4];
    #pragma unroll
    for (int q = 0; q < 4; q++) {
        float a = y[q * 2], b = y[q * 2 + 1];
        hi[q] = packbf(a, b);
        float2 f = __bfloat1622float2(*(__nv_bfloat162*)&hi[q]);
        lo[q] = packbf(a - f.x, b - f.y);
    }
    size_t ob = ((size_t)n * D + s * 8) * 2;     // byte offset
    *(uint4*)((char*)g_a1 + ob) = make_uint4(hi[0], hi[1], hi[2], hi[3]);
    *(uint4*)((char*)g_a2 + ob) = make_uint4(lo[0], lo[1], lo[2], lo[3]);
}

// ---------------- k_wprepall: all 4 layers' W -> split bf16 [DO][K] --------
__global__ void k_wprepall(const float* __restrict__ W0, const float* __restrict__ W1,
                           const float* __restrict__ W2, const float* __restrict__ W3) {
    int i = blockIdx.x * blockDim.x + threadIdx.x;
    const float* W; int K, DO, l, idx;
    if (i < 24576)       { W = W0; K = 128; DO = 192; l = 0; idx = i; }
    else if (i < 61440)  { W = W1; K = 192; DO = 192; l = 1; idx = i - 24576; }
    else if (i < 98304)  { W = W2; K = 192; DO = 192; l = 2; idx = i - 61440; }
    else if (i < 122880) { W = W3; K = 192; DO = 128; l = 3; idx = i - 98304; }
    else return;
    int k = idx / DO, n = idx % DO;
    float w = W[idx];
    __nv_bfloat16 h = __float2bfloat16(w);
    float r = w - __bfloat162float(h);
    g_w1tA[l][n * K + k] = h;
    g_w2tA[l][n * K + k] = __float2bfloat16(r);
}

// ---------------- HMMA GEMM: ldmatrix fragments + prefetch pipeline --------
#define MMA_BF16(d, a, b0_, b1_) \
    asm volatile("mma.sync.aligned.m16n8k16.row.col.f32.bf16.bf16.f32 " \
        "{%0,%1,%2,%3}, {%4,%5,%6,%7}, {%8,%9}, {%0,%1,%2,%3};" \
        : "+f"((d)[0]), "+f"((d)[1]), "+f"((d)[2]), "+f"((d)[3]) \
        : "r"((a)[0]), "r"((a)[1]), "r"((a)[2]), "r"((a)[3]), \
          "r"(b0_), "r"(b1_))

template <int K, int DO>
__global__ __launch_bounds__(256) void k_gemm(const float* __restrict__ bias, int wl) {
    float* C = g_bufC;
    const __nv_bfloat16* w1t = g_w1tA[wl];
    const __nv_bfloat16* w2t = g_w2tA[wl];
    __shared__ char As1[128 * 80];
    __shared__ char As2[128 * 80];
    __shared__ char Bs1[64 * 80];
    __shared__ char Bs2[64 * 80];

    int tid = threadIdx.x;
    int lane = tid & 31, wid = tid >> 5;
    int g = lane >> 2, t = lane & 3;
    int wm = wid & 3, wn = wid >> 2;
    int bm = blockIdx.x * 128;
    int bn = blockIdx.y * 64;

    uint32_t sA1 = (uint32_t)__cvta_generic_to_shared(As1);
    uint32_t sA2 = (uint32_t)__cvta_generic_to_shared(As2);
    uint32_t sB1 = (uint32_t)__cvta_generic_to_shared(Bs1);
    uint32_t sB2 = (uint32_t)__cvta_generic_to_shared(Bs2);
    uint32_t laneA = (uint32_t)((lane & 15) * 80 + (lane >> 4) * 16);
    uint32_t laneB = (uint32_t)((lane & 7) * 80 + ((lane >> 3) & 1) * 16 +
                                (lane >> 4) * (8 * 80));

    // per-thread load coordinates (constant across chunks)
    int arow0 = (tid * 2) >> 2, ach0 = (tid * 2) & 3;
    int arow1 = (tid * 2 + 1) >> 2, ach1 = (tid * 2 + 1) & 3;
    int brow = tid >> 2, bch = tid & 3;
    bool aok0 = (bm + arow0) < N_NODES;
    bool aok1 = (bm + arow1) < N_NODES;

    float acc[2][4][4];
    #pragma unroll
    for (int i = 0; i < 2; i++)
        #pragma unroll
        for (int j = 0; j < 4; j++)
            #pragma unroll
            for (int q = 0; q < 4; q++) acc[i][j][q] = 0.f;

    constexpr int NCHUNK = K / 32;

    // prefetch registers
    uint4 pA1[2], pA2[2], pB1, pB2;
    {   // chunk 0
        size_t g0 = ((size_t)(bm + arow0) * K) * 2 + ach0 * 16;
        size_t g1 = ((size_t)(bm + arow1) * K) * 2 + ach1 * 16;
        pA1[0] = aok0 ? __ldg((const uint4*)((const char*)g_a1 + g0)) : make_uint4(0,0,0,0);
        pA2[0] = aok0 ? __ldg((const uint4*)((const char*)g_a2 + g0)) : make_uint4(0,0,0,0);
        pA1[1] = aok1 ? __ldg((const uint4*)((const char*)g_a1 + g1)) : make_uint4(0,0,0,0);
        pA2[1] = aok1 ? __ldg((const uint4*)((const char*)g_a2 + g1)) : make_uint4(0,0,0,0);
        size_t gb = ((size_t)(bn + brow) * K) * 2 + bch * 16;
        pB1 = __ldg((const uint4*)((const char*)w1t + gb));
        pB2 = __ldg((const uint4*)((const char*)w2t + gb));
    }

    for (int c = 0; c < NCHUNK; c++) {
        // store prefetched chunk c to smem
        *(uint4*)(As1 + arow0 * 80 + ach0 * 16) = pA1[0];
        *(uint4*)(As2 + arow0 * 80 + ach0 * 16) = pA2[0];
        *(uint4*)(As1 + arow1 * 80 + ach1 * 16) = pA1[1];
        *(uint4*)(As2 + arow1 * 80 + ach1 * 16) = pA2[1];
        *(uint4*)(Bs1 + brow * 80 + bch * 16) = pB1;
        *(uint4*)(Bs2 + brow * 80 + bch * 16) = pB2;
        __syncthreads();

        // issue global loads for chunk c+1 (overlap with MMA below)
        if (c + 1 < NCHUNK) {
            int cc = (c + 1) * 32;
            size_t g0 = ((size_t)(bm + arow0) * K + cc) * 2 + ach0 * 16;
            size_t g1 = ((size_t)(bm + arow1) * K + cc) * 2 + ach1 * 16;
            pA1[0] = aok0 ? __ldg((const uint4*)((const char*)g_a1 + g0)) : make_uint4(0,0,0,0);
            pA2[0] = aok0 ? __ldg((const uint4*)((const char*)g_a2 + g0)) : make_uint4(0,0,0,0);
            pA1[1] = aok1 ? __ldg((const uint4*)((const char*)g_a1 + g1)) : make_uint4(0,0,0,0);
            pA2[1] = aok1 ? __ldg((const uint4*)((const char*)g_a2 + g1)) : make_uint4(0,0,0,0);
            size_t gb = ((size_t)(bn + brow) * K + cc) * 2 + bch * 16;
            pB1 = __ldg((const uint4*)((const char*)w1t + gb));
            pB2 = __ldg((const uint4*)((const char*)w2t + gb));
        }

        #pragma unroll
        for (int ks = 0; ks < 2; ks++) {
            uint32_t kb = (uint32_t)(ks * 32);
            uint32_t a1f[2][4], a2f[2][4];
            #pragma unroll
            for (int mt = 0; mt < 2; mt++) {
                uint32_t ab = (uint32_t)((wm * 32 + mt * 16) * 80) + kb + laneA;
                ldsm_x4(a1f[mt], sA1 + ab);
                ldsm_x4(a2f[mt], sA2 + ab);
            }
            uint32_t bv1[2][4], bv2[2][4];
            #pragma unroll
            for (int p = 0; p < 2; p++) {
                uint32_t bb = (uint32_t)((wn * 32 + p * 16) * 80) + kb + laneB;
                ldsm_x4(bv1[p], sB1 + bb);
                ldsm_x4(bv2[p], sB2 + bb);
            }
            #pragma unroll
            for (int nt = 0; nt < 4; nt++) {
                uint32_t b10 = bv1[nt >> 1][(nt & 1) * 2];
                uint32_t b11 = bv1[nt >> 1][(nt & 1) * 2 + 1];
                uint32_t b20 = bv2[nt >> 1][(nt & 1) * 2];
                uint32_t b21 = bv2[nt >> 1][(nt & 1) * 2 + 1];
                #pragma unroll
                for (int mt = 0; mt < 2; mt++) {
                    MMA_BF16(acc[mt][nt], a1f[mt], b10, b11);
                    MMA_BF16(acc[mt][nt], a1f[mt], b20, b21);
                    MMA_BF16(acc[mt][nt], a2f[mt], b10, b11);
                }
            }
        }
        __syncthreads();
    }

    // epilogue: fp32 C + relu'd fp16 copy into g_h
    #pragma unroll
    for (int nt = 0; nt < 4; nt++) {
        int col = bn + wn * 32 + nt * 8 + 2 * t;
        float2 bv = *(const float2*)(bias + col);
        #pragma unroll
        for (int mt = 0; mt < 2; mt++) {
            int r0 = bm + wm * 32 + mt * 16 + g;
            if (r0 < N_NODES) {
                float2 o = make_float2(acc[mt][nt][0] + bv.x, acc[mt][nt][1] + bv.y);
                *(float2*)(C + (size_t)r0 * DO + col) = o;
                *(uint32_t*)((char*)g_h + ((size_t)r0 * DO + col) * 2) = packh_relu(o.x, o.y);
            }
            int r1 = r0 + 8;
            if (r1 < N_NODES) {
                float2 o = make_float2(acc[mt][nt][2] + bv.x, acc[mt][nt][3] + bv.y);
                *(float2*)(C + (size_t)r1 * DO + col) = o;
                *(uint32_t*)((char*)g_h + ((size_t)r1 * DO + col) * 2) = packh_relu(o.x, o.y);
            }
        }
    }
}

// ---------------- pooling (+ tail re-zero of g_deg for next call) ----------
__global__ void k_pool() {
    int gid = ((blockIdx.y * gridDim.x + blockIdx.x) * blockDim.x) + threadIdx.x;
    int nthreads = gridDim.x * gridDim.y * blockDim.x;   // 32768
    for (int i = gid; i < N_NODES; i += nthreads) g_deg[i] = 0;

    const float* H = g_bufC;                 // final layer output, d=128
    int g = blockIdx.x, chunk = blockIdx.y;  // 64 x 4
    int s = g_gstart[g], e = g_gstart[g + 1];
    int len = e - s;
    int n0 = s + (len * chunk) / 4;
    int n1 = s + (len * (chunk + 1)) / 4;
    int f = threadIdx.x;                     // 128 features
    float a0 = 0.f, a1 = 0.f, a2 = 0.f, a3 = 0.f;
    int n = n0;
    for (; n + 4 <= n1; n += 4) {
        a0 += __ldg(H + (size_t)(n + 0) * 128 + f);
        a1 += __ldg(H + (size_t)(n + 1) * 128 + f);
        a2 += __ldg(H + (size_t)(n + 2) * 128 + f);
        a3 += __ldg(H + (size_t)(n + 3) * 128 + f);
    }
    for (; n < n1; n++) a0 += __ldg(H + (size_t)n * 128 + f);
    g_pool_sum4[(chunk * N_GRAPHS + g) * 128 + f] = (a0 + a1) + (a2 + a3);
}

__global__ void k_head(const float* __restrict__ Wfc, const float* __restrict__ bfc,
                       float* __restrict__ out) {
    __shared__ float s_logit[N_GRAPHS][10];
    __shared__ float s_lse[N_GRAPHS];
    int tid = threadIdx.x;                   // 640 threads
    int g = tid / 10, j = tid % 10;
    float cnt = fmaxf((float)(g_gstart[g + 1] - g_gstart[g]), 1.f);
    float acc = bfc[j];
    #pragma unroll 8
    for (int f = 0; f < 128; f++) {
        float s = g_pool_sum4[(0 * N_GRAPHS + g) * 128 + f]
                + g_pool_sum4[(1 * N_GRAPHS + g) * 128 + f]
                + g_pool_sum4[(2 * N_GRAPHS + g) * 128 + f]
                + g_pool_sum4[(3 * N_GRAPHS + g) * 128 + f];
        acc += (s / cnt) * Wfc[f * 10 + j];
    }
    s_logit[g][j] = acc;
    __syncthreads();
    if (j == 0) {
        float m = -1e30f;
        #pragma unroll
        for (int t = 0; t < 10; t++) m = fmaxf(m, s_logit[g][t]);
        float s = 0.f;
        #pragma unroll
        for (int t = 0; t < 10; t++) s += expf(s_logit[g][t] - m);
        s_lse[g] = m + logf(s);
    }
    __syncthreads();
    out[g * 10 + j] = s_logit[g][j] - s_lse[g];
}

// ---------------- launch ----------------
extern "C" void kernel_launch(void* const* d_in, const int* in_sizes, int n_in,
                              void* d_out, int out_size) {
    const float* x   = (const float*)d_in[0];
    const float* W0  = (const float*)d_in[1];
    const float* b0  = (const float*)d_in[2];
    const float* W1  = (const float*)d_in[3];
    const float* b1  = (const float*)d_in[4];
    const float* W2  = (const float*)d_in[5];
    const float* b2  = (const float*)d_in[6];
    const float* W3  = (const float*)d_in[7];
    const float* b3  = (const float*)d_in[8];
    const float* Wfc = (const float*)d_in[9];
    const float* bfc = (const float*)d_in[10];
    const int* ei    = (const int*)d_in[11];
    const int* batch = (const int*)d_in[12];
    const int* src = ei;
    const int* dst = ei + N_EDGES;
    float* out = (float*)d_out;

    int agg128_blocks = (N_NODES * 16 + 255) / 256;   // 6250
    int agg192_blocks = (N_NODES * 24 + 255) / 256;   // 9375
    dim3 g192((N_NODES + 127) / 128, 3);
    dim3 g128((N_NODES + 127) / 128, 2);

    k_prep<<<NB_H + NB_X + NB_G, 256>>>(dst, x, batch);        // 0
    k_scan1<<<NB_SCAN, SCAN_B>>>();                            // 1
    k_scan2<<<1, 128>>>();                                     // 2
    k_scan3<<<NB_SCAN, SCAN_B>>>();                            // 3
    k_fill<<<(N_EDGES + 255) / 256, 256>>>(src, dst);          // 4
    k_wprepall<<<480, 256>>>(W0, W1, W2, W3);                  // 5
    k_agg<128><<<agg128_blocks, 256>>>(x);                     // 6
    k_gemm<128, 192><<<g192, 256>>>(b0, 0);                    // 7
    k_agg<192><<<agg192_blocks, 256>>>(nullptr);               // 8
    k_gemm<192, 192><<<g192, 256>>>(b1, 1);                    // 9
    k_agg<192><<<agg192_blocks, 256>>>(nullptr);               // 10
    k_gemm<192, 192><<<g192, 256>>>(b2, 2);                    // 11
    k_agg<192><<<agg192_blocks, 256>>>(nullptr);               // 12
    k_gemm<192, 128><<<g128, 256>>>(b3, 3);                    // 13
    dim3 pool_grid(N_GRAPHS, 4);
    k_pool<<<pool_grid, 128>>>();                              // 14
    k_head<<<1, 640>>>(Wfc, bfc, out);                         // 15
}